// round 1
// baseline (speedup 1.0000x reference)
#include <cuda_runtime.h>
#include <cstddef>

// ---------------- problem constants ----------------
#define BATCH   4
#define SEQ     32768
#define NCH     256
#define LKER    16
#define STR     8
#define LF      4095          // (SEQ - LKER)/STR + 1
#define NBLK    4
#define NP      3
#define KKER    3
#define CRDIM   64
#define EPSLN   1e-5f

// ---------------- scratch (device globals; no runtime alloc) ----------------
__device__ float g_enc[BATCH * LF * NCH];
__device__ float g_x  [BATCH * LF * NCH];
__device__ float g_xn [BATCH * LF * NCH];
__device__ float g_m0 [BATCH * LF * NCH];
__device__ float g_m1 [BATCH * LF * NCH];
__device__ float g_weff[NBLK * NP * KKER * NCH];
__device__ float g_beff[NBLK * NP * KKER];
__device__ float g_dwt [LKER * NCH];          // transposed decoder weight [j][n]
__device__ float g_of  [BATCH * LF * LKER];   // per-frame decoder partials

__device__ __forceinline__ float warp_sum(float v) {
#pragma unroll
    for (int o = 16; o; o >>= 1) v += __shfl_xor_sync(0xffffffffu, v, o);
    return v;
}

// ---------------- W_eff = w2 @ w1, b_eff = w2 @ b1 + b2 ----------------
__global__ void weff_kernel(const float* __restrict__ w1, const float* __restrict__ b1,
                            const float* __restrict__ w2, const float* __restrict__ b2) {
    int bpk = blockIdx.x;              // 0 .. NBLK*NP*KKER-1
    int k   = bpk % KKER;
    int bp  = bpk / KKER;              // 0..11
    int c   = threadIdx.x;             // 0..255
    const float* w1p = w1 + (size_t)bp * CRDIM * NCH;
    const float* w2p = w2 + (size_t)bp * KKER * CRDIM + (size_t)k * CRDIM;
    float s = 0.f;
#pragma unroll 4
    for (int r = 0; r < CRDIM; r++) s += w2p[r] * w1p[(size_t)r * NCH + c];
    g_weff[(size_t)bpk * NCH + c] = s;
    if (c == 0) {
        float sb = b2[bp * KKER + k];
        const float* b1p = b1 + bp * CRDIM;
        for (int r = 0; r < CRDIM; r++) sb += w2p[r] * b1p[r];
        g_beff[bpk] = sb;
    }
}

// ---------------- transpose decoder weight ----------------
__global__ void decwt_kernel(const float* __restrict__ dec_w) {
    int j = blockIdx.x;        // 0..15
    int n = threadIdx.x;       // 0..255
    g_dwt[j * NCH + n] = dec_w[n * LKER + j];
}

// ---------------- encoder conv (ac+bc) + channel LayerNorm, frame-major out ----------------
#define ENC_FPB 16
__global__ void enc_ln_kernel(const float* __restrict__ ac, const float* __restrict__ bc,
                              const float* __restrict__ acw, const float* __restrict__ bcw,
                              const float* __restrict__ gam, const float* __restrict__ bet) {
    const int b   = blockIdx.y;
    const int f0  = blockIdx.x * ENC_FPB;
    const int tid = threadIdx.x;
    __shared__ float s_ac[ENC_FPB * STR + LKER - STR];   // 136
    __shared__ float s_bc[ENC_FPB * STR + LKER - STR];
    __shared__ float s_enc[ENC_FPB][NCH];
    __shared__ float s_mu[ENC_FPB], s_rs[ENC_FPB];

    const int base = f0 * STR;
    const int WLEN = ENC_FPB * STR + LKER - STR;
    for (int i = tid; i < WLEN; i += 256) {
        int idx = base + i;
        s_ac[i] = (idx < SEQ) ? ac[(size_t)b * SEQ + idx] : 0.f;
        s_bc[i] = (idx < SEQ) ? bc[(size_t)b * SEQ + idx] : 0.f;
    }
    float wa[LKER], wb[LKER];
#pragma unroll
    for (int t = 0; t < LKER; t++) { wa[t] = acw[tid * LKER + t]; wb[t] = bcw[tid * LKER + t]; }
    __syncthreads();

    const int nf = min(ENC_FPB, LF - f0);
    for (int fl = 0; fl < nf; fl++) {
        float acc = 0.f;
        int o = fl * STR;
#pragma unroll
        for (int t = 0; t < LKER; t++) acc += wa[t] * s_ac[o + t] + wb[t] * s_bc[o + t];
        s_enc[fl][tid] = acc;
    }
    __syncthreads();

    const int wid = tid >> 5, lane = tid & 31;
    for (int fl = wid; fl < nf; fl += 8) {
        float s = 0.f, s2 = 0.f;
#pragma unroll
        for (int i = 0; i < 8; i++) { float v = s_enc[fl][lane + 32 * i]; s += v; s2 += v * v; }
        s = warp_sum(s); s2 = warp_sum(s2);
        if (lane == 0) {
            float mu = s * (1.f / NCH);
            s_mu[fl] = mu;
            s_rs[fl] = rsqrtf(s2 * (1.f / NCH) - mu * mu + EPSLN);
        }
    }
    __syncthreads();

    const size_t ob = ((size_t)b * LF + f0) * NCH;
    const float gn = gam[tid], bn = bet[tid];
    for (int fl = 0; fl < nf; fl++) {
        float e = s_enc[fl][tid];
        g_enc[ob + (size_t)fl * NCH + tid] = e;
        g_x  [ob + (size_t)fl * NCH + tid] = (e - s_mu[fl]) * s_rs[fl] * gn + bn;
    }
}

// ---------------- fused scalar-PReLU + channel LayerNorm ----------------
__global__ void prelu_ln_kernel(const float* __restrict__ x, float* __restrict__ xn,
                                const float* __restrict__ act_a,
                                const float* __restrict__ gam, const float* __restrict__ bet,
                                int blk) {
    const int b = blockIdx.y;
    const int f0 = blockIdx.x * 32;
    const int wid = threadIdx.x >> 5, lane = threadIdx.x & 31;
    const float alpha = act_a[blk];
    for (int fl = wid; fl < 32; fl += 8) {
        int f = f0 + fl;
        if (f >= LF) break;                      // warp-uniform
        size_t off = ((size_t)b * LF + f) * NCH;
        float v[8]; float s = 0.f, s2 = 0.f;
#pragma unroll
        for (int i = 0; i < 8; i++) {
            float t = x[off + lane + 32 * i];
            t = (t >= 0.f) ? t : alpha * t;
            v[i] = t; s += t; s2 += t * t;
        }
        s = warp_sum(s); s2 = warp_sum(s2);
        float mu = s * (1.f / NCH);
        float rs = rsqrtf(s2 * (1.f / NCH) - mu * mu + EPSLN);
#pragma unroll
        for (int i = 0; i < 8; i++) {
            int c = lane + 32 * i;
            xn[off + c] = (v[i] - mu) * rs * gam[c] + bet[c];
        }
    }
}

// ---------------- involution: ker = W_eff @ m + b_eff; out = sum_k ker*shift(m); PReLU ----------------
#define INV_FPB 32
__global__ void inv_kernel(const float* __restrict__ min_, float* __restrict__ mout,
                           const float* __restrict__ prelu_a, int blk, int p) {
    const int b = blockIdx.y;
    const int f0 = blockIdx.x * INV_FPB;
    const int tid = threadIdx.x;
    __shared__ __align__(16) float sm[INV_FPB + 2][NCH];
    __shared__ float sw[KKER][NCH];
    __shared__ float sker[INV_FPB][KKER];
    __shared__ float sbe[KKER];

    const int bp = blk * NP + p;
#pragma unroll
    for (int k = 0; k < KKER; k++) sw[k][tid] = g_weff[((size_t)bp * KKER + k) * NCH + tid];
    if (tid < KKER) sbe[tid] = g_beff[bp * KKER + tid];

    for (int r = 0; r < INV_FPB + 2; r++) {
        int f = f0 - 1 + r;
        sm[r][tid] = (f >= 0 && f < LF) ? min_[((size_t)b * LF + f) * NCH + tid] : 0.f;
    }
    __syncthreads();

    const int nf = min(INV_FPB, LF - f0);
    const int wid = tid >> 5, lane = tid & 31;
    for (int t = wid; t < nf * KKER; t += 8) {
        int fl = t / KKER, k = t - fl * KKER;
        float s = 0.f;
#pragma unroll
        for (int i = 0; i < 8; i++) s += sw[k][lane + 32 * i] * sm[fl + 1][lane + 32 * i];
        s = warp_sum(s);
        if (lane == 0) sker[fl][k] = s + sbe[k];
    }
    __syncthreads();

    const float a = prelu_a[(size_t)bp * NCH + tid];
    const size_t ob = ((size_t)b * LF + f0) * NCH;
    for (int fl = 0; fl < nf; fl++) {
        float o = sker[fl][0] * sm[fl][tid] + sker[fl][1] * sm[fl + 1][tid]
                + sker[fl][2] * sm[fl + 2][tid];
        o = (o >= 0.f) ? o : a * o;
        mout[ob + (size_t)fl * NCH + tid] = o;
    }
}

// ---------------- tiled SGEMM: C[b][m][o] = A[b][m][:] . W[o][:] (+bias)(+D)(relu)(*E) ----------------
#define BM 64
#define BN 64
#define BK 32
template <bool RELU, bool ADDD, bool MULE>
__global__ void __launch_bounds__(256)
gemm_kernel(const float* __restrict__ A, const float* __restrict__ W,
            const float* __restrict__ bias, const float* __restrict__ D,
            const float* __restrict__ E, float* __restrict__ C, int Nout) {
    const int b  = blockIdx.z;
    const int m0 = blockIdx.x * BM;
    const int n0 = blockIdx.y * BN;
    const float* Ab = A + (size_t)b * LF * NCH;
    float* Cb = C + (size_t)b * LF * Nout;

    __shared__ __align__(16) float As[BK][BM + 4];
    __shared__ __align__(16) float Ws[BK][BN + 4];

    const int tid = threadIdx.x;
    const int tx = tid & 15;   // n-group
    const int ty = tid >> 4;   // m-group
    float acc[4][4] = {};

    for (int k0 = 0; k0 < NCH; k0 += BK) {
#pragma unroll
        for (int i = 0; i < 2; i++) {
            int idx = tid + i * 256;       // 0..511
            int row = idx >> 3;            // 0..63
            int c4  = idx & 7;             // float4 column
            float4 v = make_float4(0.f, 0.f, 0.f, 0.f);
            int m = m0 + row;
            if (m < LF) v = *reinterpret_cast<const float4*>(Ab + (size_t)m * NCH + k0 + c4 * 4);
            As[c4 * 4 + 0][row] = v.x; As[c4 * 4 + 1][row] = v.y;
            As[c4 * 4 + 2][row] = v.z; As[c4 * 4 + 3][row] = v.w;
        }
#pragma unroll
        for (int i = 0; i < 2; i++) {
            int idx = tid + i * 256;
            int row = idx >> 3;
            int c4  = idx & 7;
            float4 v = make_float4(0.f, 0.f, 0.f, 0.f);
            int n = n0 + row;
            if (n < Nout) v = *reinterpret_cast<const float4*>(W + (size_t)n * NCH + k0 + c4 * 4);
            Ws[c4 * 4 + 0][row] = v.x; Ws[c4 * 4 + 1][row] = v.y;
            Ws[c4 * 4 + 2][row] = v.z; Ws[c4 * 4 + 3][row] = v.w;
        }
        __syncthreads();
#pragma unroll
        for (int k = 0; k < BK; k++) {
            const float4 ra = *reinterpret_cast<const float4*>(&As[k][ty * 4]);
            const float4 rb = *reinterpret_cast<const float4*>(&Ws[k][tx * 4]);
            const float a4[4] = {ra.x, ra.y, ra.z, ra.w};
            const float b4[4] = {rb.x, rb.y, rb.z, rb.w};
#pragma unroll
            for (int i = 0; i < 4; i++)
#pragma unroll
                for (int j = 0; j < 4; j++) acc[i][j] += a4[i] * b4[j];
        }
        __syncthreads();
    }

#pragma unroll
    for (int i = 0; i < 4; i++) {
        int m = m0 + ty * 4 + i;
        if (m >= LF) continue;
#pragma unroll
        for (int j = 0; j < 4; j++) {
            int n = n0 + tx * 4 + j;
            if (n >= Nout) continue;
            float v = acc[i][j];
            if (bias) v += bias[n];
            if (ADDD) v += D[((size_t)b * LF + m) * Nout + n];
            if (RELU) v = fmaxf(v, 0.f);
            if (MULE) v *= E[((size_t)b * LF + m) * Nout + n];
            Cb[(size_t)m * Nout + n] = v;
        }
    }
}

// ---------------- transposed-conv overlap-add ----------------
__global__ void ola_kernel(float* __restrict__ out) {
    const int b = blockIdx.y;
    const int t = blockIdx.x * 256 + threadIdx.x;
    if (t >= SEQ) return;
    const int f0 = t >> 3;
    const int j0 = t & 7;
    float v = 0.f;
    if (f0 < LF)  v += g_of[((size_t)b * LF + f0) * LKER + j0];
    if (f0 >= 1)  v += g_of[((size_t)b * LF + f0 - 1) * LKER + j0 + 8];
    out[(size_t)b * SEQ + t] = v;
}

// ---------------- driver ----------------
extern "C" void kernel_launch(void* const* d_in, const int* in_sizes, int n_in,
                              void* d_out, int out_size) {
    const float* noisy_ac    = (const float*)d_in[0];
    const float* noisy_bc    = (const float*)d_in[1];
    const float* ac_w        = (const float*)d_in[2];
    const float* bc_w        = (const float*)d_in[3];
    const float* me_ln_g     = (const float*)d_in[4];
    const float* me_ln_b     = (const float*)d_in[5];
    const float* me_init_w   = (const float*)d_in[6];
    const float* me_init_b   = (const float*)d_in[7];
    const float* blk_ln_g    = (const float*)d_in[8];
    const float* blk_ln_b    = (const float*)d_in[9];
    const float* blk_act_a   = (const float*)d_in[10];
    const float* inv_w1      = (const float*)d_in[11];
    const float* inv_b1      = (const float*)d_in[12];
    const float* inv_w2      = (const float*)d_in[13];
    const float* inv_b2      = (const float*)d_in[14];
    const float* inv_prelu_a = (const float*)d_in[15];
    const float* skip_w      = (const float*)d_in[16];
    const float* skip_b      = (const float*)d_in[17];
    const float* me_final_w  = (const float*)d_in[18];
    const float* me_final_b  = (const float*)d_in[19];
    const float* dec_w       = (const float*)d_in[20];
    float* out = (float*)d_out;

    float *enc, *x, *xn, *m0, *m1, *of, *dwt;
    cudaGetSymbolAddress((void**)&enc, g_enc);
    cudaGetSymbolAddress((void**)&x,   g_x);
    cudaGetSymbolAddress((void**)&xn,  g_xn);
    cudaGetSymbolAddress((void**)&m0,  g_m0);
    cudaGetSymbolAddress((void**)&m1,  g_m1);
    cudaGetSymbolAddress((void**)&of,  g_of);
    cudaGetSymbolAddress((void**)&dwt, g_dwt);

    // parameter prep
    weff_kernel<<<NBLK * NP * KKER, NCH>>>(inv_w1, inv_b1, inv_w2, inv_b2);
    decwt_kernel<<<LKER, NCH>>>(dec_w);

    // encoder + LN  (writes g_enc, g_x)
    enc_ln_kernel<<<dim3((LF + ENC_FPB - 1) / ENC_FPB, BATCH), 256>>>(
        noisy_ac, noisy_bc, ac_w, bc_w, me_ln_g, me_ln_b);

    // me_init pointwise: g_x -> g_m0   ("x" state lives in g_m0 at loop top)
    gemm_kernel<false, false, false><<<dim3(64, 4, BATCH), 256>>>(
        x, me_init_w, me_init_b, nullptr, nullptr, m0, NCH);

    for (int blk = 0; blk < NBLK; blk++) {
        prelu_ln_kernel<<<dim3((LF + 31) / 32, BATCH), 256>>>(
            m0, xn, blk_act_a, blk_ln_g + blk * NCH, blk_ln_b + blk * NCH, blk);
        inv_kernel<<<dim3((LF + INV_FPB - 1) / INV_FPB, BATCH), 256>>>(xn, x,  inv_prelu_a, blk, 0);
        inv_kernel<<<dim3((LF + INV_FPB - 1) / INV_FPB, BATCH), 256>>>(x,  m1, inv_prelu_a, blk, 1);
        inv_kernel<<<dim3((LF + INV_FPB - 1) / INV_FPB, BATCH), 256>>>(m1, x,  inv_prelu_a, blk, 2);
        // x_new = m (in g_x) + skip(xn)  -> g_m0
        gemm_kernel<false, true, false><<<dim3(64, 4, BATCH), 256>>>(
            xn, skip_w + (size_t)blk * NCH * NCH, skip_b + blk * NCH, x, nullptr, m0, NCH);
    }

    // masked = relu(me_final(x)) * enc  -> g_xn
    gemm_kernel<true, false, true><<<dim3(64, 4, BATCH), 256>>>(
        m0, me_final_w, me_final_b, nullptr, enc, xn, NCH);

    // decoder partials OF[f][j] = masked[f][:] . dec_w[:,j]  -> g_of
    gemm_kernel<false, false, false><<<dim3(64, 1, BATCH), 256>>>(
        xn, dwt, nullptr, nullptr, nullptr, of, LKER);

    // overlap-add -> output
    ola_kernel<<<dim3(SEQ / 256, BATCH), 256>>>(out);
}

// round 2
// speedup vs baseline: 1.0006x; 1.0006x over previous
#include <cuda_runtime.h>
#include <cstddef>

// ---------------- problem constants ----------------
#define BATCH   4
#define SEQ     32768
#define NCH     256
#define LKER    16
#define STR     8
#define LF      4095          // (SEQ - LKER)/STR + 1
#define NBLK    4
#define NP      3
#define KKER    3
#define CRDIM   64
#define EPSLN   1e-5f

// ---------------- scratch (device globals; no runtime alloc) ----------------
__device__ float g_enc[BATCH * LF * NCH];
__device__ float g_x  [BATCH * LF * NCH];
__device__ float g_xn [BATCH * LF * NCH];
__device__ float g_m0 [BATCH * LF * NCH];
__device__ float g_m1 [BATCH * LF * NCH];
__device__ float g_weff[NBLK * NP * KKER * NCH];
__device__ float g_beff[NBLK * NP * KKER];
__device__ float g_dwt [LKER * NCH];          // transposed decoder weight [j][n]
__device__ float g_of  [BATCH * LF * LKER];   // per-frame decoder partials

__device__ __forceinline__ float warp_sum(float v) {
#pragma unroll
    for (int o = 16; o; o >>= 1) v += __shfl_xor_sync(0xffffffffu, v, o);
    return v;
}

// ---------------- W_eff = w2 @ w1, b_eff = w2 @ b1 + b2 ----------------
__global__ void weff_kernel(const float* __restrict__ w1, const float* __restrict__ b1,
                            const float* __restrict__ w2, const float* __restrict__ b2) {
    int bpk = blockIdx.x;              // 0 .. NBLK*NP*KKER-1
    int k   = bpk % KKER;
    int bp  = bpk / KKER;              // 0..11
    int c   = threadIdx.x;             // 0..255
    const float* w1p = w1 + (size_t)bp * CRDIM * NCH;
    const float* w2p = w2 + (size_t)bp * KKER * CRDIM + (size_t)k * CRDIM;
    float s = 0.f;
#pragma unroll 4
    for (int r = 0; r < CRDIM; r++) s += w2p[r] * w1p[(size_t)r * NCH + c];
    g_weff[(size_t)bpk * NCH + c] = s;
    if (c == 0) {
        float sb = b2[bp * KKER + k];
        const float* b1p = b1 + bp * CRDIM;
        for (int r = 0; r < CRDIM; r++) sb += w2p[r] * b1p[r];
        g_beff[bpk] = sb;
    }
}

// ---------------- transpose decoder weight ----------------
__global__ void decwt_kernel(const float* __restrict__ dec_w) {
    int j = blockIdx.x;        // 0..15
    int n = threadIdx.x;       // 0..255
    g_dwt[j * NCH + n] = dec_w[n * LKER + j];
}

// ---------------- encoder conv (ac+bc) + channel LayerNorm, frame-major out ----------------
#define ENC_FPB 16
__global__ void enc_ln_kernel(const float* __restrict__ ac, const float* __restrict__ bc,
                              const float* __restrict__ acw, const float* __restrict__ bcw,
                              const float* __restrict__ gam, const float* __restrict__ bet) {
    const int b   = blockIdx.y;
    const int f0  = blockIdx.x * ENC_FPB;
    const int tid = threadIdx.x;
    __shared__ float s_ac[ENC_FPB * STR + LKER - STR];   // 136
    __shared__ float s_bc[ENC_FPB * STR + LKER - STR];
    __shared__ float s_enc[ENC_FPB][NCH];
    __shared__ float s_mu[ENC_FPB], s_rs[ENC_FPB];

    const int base = f0 * STR;
    const int WLEN = ENC_FPB * STR + LKER - STR;
    for (int i = tid; i < WLEN; i += 256) {
        int idx = base + i;
        s_ac[i] = (idx < SEQ) ? ac[(size_t)b * SEQ + idx] : 0.f;
        s_bc[i] = (idx < SEQ) ? bc[(size_t)b * SEQ + idx] : 0.f;
    }
    float wa[LKER], wb[LKER];
#pragma unroll
    for (int t = 0; t < LKER; t++) { wa[t] = acw[tid * LKER + t]; wb[t] = bcw[tid * LKER + t]; }
    __syncthreads();

    const int nf = min(ENC_FPB, LF - f0);
    for (int fl = 0; fl < nf; fl++) {
        float acc = 0.f;
        int o = fl * STR;
#pragma unroll
        for (int t = 0; t < LKER; t++) acc += wa[t] * s_ac[o + t] + wb[t] * s_bc[o + t];
        s_enc[fl][tid] = acc;
    }
    __syncthreads();

    const int wid = tid >> 5, lane = tid & 31;
    for (int fl = wid; fl < nf; fl += 8) {
        float s = 0.f, s2 = 0.f;
#pragma unroll
        for (int i = 0; i < 8; i++) { float v = s_enc[fl][lane + 32 * i]; s += v; s2 += v * v; }
        s = warp_sum(s); s2 = warp_sum(s2);
        if (lane == 0) {
            float mu = s * (1.f / NCH);
            s_mu[fl] = mu;
            s_rs[fl] = rsqrtf(s2 * (1.f / NCH) - mu * mu + EPSLN);
        }
    }
    __syncthreads();

    const size_t ob = ((size_t)b * LF + f0) * NCH;
    const float gn = gam[tid], bn = bet[tid];
    for (int fl = 0; fl < nf; fl++) {
        float e = s_enc[fl][tid];
        g_enc[ob + (size_t)fl * NCH + tid] = e;
        g_x  [ob + (size_t)fl * NCH + tid] = (e - s_mu[fl]) * s_rs[fl] * gn + bn;
    }
}

// ---------------- fused scalar-PReLU + channel LayerNorm ----------------
__global__ void prelu_ln_kernel(const float* __restrict__ x, float* __restrict__ xn,
                                const float* __restrict__ act_a,
                                const float* __restrict__ gam, const float* __restrict__ bet,
                                int blk) {
    const int b = blockIdx.y;
    const int f0 = blockIdx.x * 32;
    const int wid = threadIdx.x >> 5, lane = threadIdx.x & 31;
    const float alpha = act_a[blk];
    for (int fl = wid; fl < 32; fl += 8) {
        int f = f0 + fl;
        if (f >= LF) break;                      // warp-uniform
        size_t off = ((size_t)b * LF + f) * NCH;
        float v[8]; float s = 0.f, s2 = 0.f;
#pragma unroll
        for (int i = 0; i < 8; i++) {
            float t = x[off + lane + 32 * i];
            t = (t >= 0.f) ? t : alpha * t;
            v[i] = t; s += t; s2 += t * t;
        }
        s = warp_sum(s); s2 = warp_sum(s2);
        float mu = s * (1.f / NCH);
        float rs = rsqrtf(s2 * (1.f / NCH) - mu * mu + EPSLN);
#pragma unroll
        for (int i = 0; i < 8; i++) {
            int c = lane + 32 * i;
            xn[off + c] = (v[i] - mu) * rs * gam[c] + bet[c];
        }
    }
}

// ---------------- involution: ker = W_eff @ m + b_eff; out = sum_k ker*shift(m); PReLU ----------------
#define INV_FPB 32
__global__ void inv_kernel(const float* __restrict__ min_, float* __restrict__ mout,
                           const float* __restrict__ prelu_a, int blk, int p) {
    const int b = blockIdx.y;
    const int f0 = blockIdx.x * INV_FPB;
    const int tid = threadIdx.x;
    __shared__ __align__(16) float sm[INV_FPB + 2][NCH];
    __shared__ float sw[KKER][NCH];
    __shared__ float sker[INV_FPB][KKER];
    __shared__ float sbe[KKER];

    const int bp = blk * NP + p;
#pragma unroll
    for (int k = 0; k < KKER; k++) sw[k][tid] = g_weff[((size_t)bp * KKER + k) * NCH + tid];
    if (tid < KKER) sbe[tid] = g_beff[bp * KKER + tid];

    for (int r = 0; r < INV_FPB + 2; r++) {
        int f = f0 - 1 + r;
        sm[r][tid] = (f >= 0 && f < LF) ? min_[((size_t)b * LF + f) * NCH + tid] : 0.f;
    }
    __syncthreads();

    const int nf = min(INV_FPB, LF - f0);
    const int wid = tid >> 5, lane = tid & 31;
    for (int t = wid; t < nf * KKER; t += 8) {
        int fl = t / KKER, k = t - fl * KKER;
        float s = 0.f;
#pragma unroll
        for (int i = 0; i < 8; i++) s += sw[k][lane + 32 * i] * sm[fl + 1][lane + 32 * i];
        s = warp_sum(s);
        if (lane == 0) sker[fl][k] = s + sbe[k];
    }
    __syncthreads();

    const float a = prelu_a[(size_t)bp * NCH + tid];
    const size_t ob = ((size_t)b * LF + f0) * NCH;
    for (int fl = 0; fl < nf; fl++) {
        float o = sker[fl][0] * sm[fl][tid] + sker[fl][1] * sm[fl + 1][tid]
                + sker[fl][2] * sm[fl + 2][tid];
        o = (o >= 0.f) ? o : a * o;
        mout[ob + (size_t)fl * NCH + tid] = o;
    }
}

// ---------------- tiled SGEMM: C[b][m][o] = A[b][m][:] . W[o][:] (+bias)(+D)(relu)(*E) ----------------
#define BM 64
#define BN 64
#define BK 32
template <bool RELU, bool ADDD, bool MULE>
__global__ void __launch_bounds__(256)
gemm_kernel(const float* __restrict__ A, const float* __restrict__ W,
            const float* __restrict__ bias, const float* __restrict__ D,
            const float* __restrict__ E, float* __restrict__ C, int Nout) {
    const int b  = blockIdx.z;
    const int m0 = blockIdx.x * BM;
    const int n0 = blockIdx.y * BN;
    const float* Ab = A + (size_t)b * LF * NCH;
    float* Cb = C + (size_t)b * LF * Nout;

    __shared__ __align__(16) float As[BK][BM + 4];
    __shared__ __align__(16) float Ws[BK][BN + 4];

    const int tid = threadIdx.x;
    const int tx = tid & 15;   // n-group
    const int ty = tid >> 4;   // m-group
    float acc[4][4] = {};

    for (int k0 = 0; k0 < NCH; k0 += BK) {
#pragma unroll
        for (int i = 0; i < 2; i++) {
            int idx = tid + i * 256;       // 0..511
            int row = idx >> 3;            // 0..63
            int c4  = idx & 7;             // float4 column
            float4 v = make_float4(0.f, 0.f, 0.f, 0.f);
            int m = m0 + row;
            if (m < LF) v = *reinterpret_cast<const float4*>(Ab + (size_t)m * NCH + k0 + c4 * 4);
            As[c4 * 4 + 0][row] = v.x; As[c4 * 4 + 1][row] = v.y;
            As[c4 * 4 + 2][row] = v.z; As[c4 * 4 + 3][row] = v.w;
        }
#pragma unroll
        for (int i = 0; i < 2; i++) {
            int idx = tid + i * 256;
            int row = idx >> 3;
            int c4  = idx & 7;
            float4 v = make_float4(0.f, 0.f, 0.f, 0.f);
            int n = n0 + row;
            if (n < Nout) v = *reinterpret_cast<const float4*>(W + (size_t)n * NCH + k0 + c4 * 4);
            Ws[c4 * 4 + 0][row] = v.x; Ws[c4 * 4 + 1][row] = v.y;
            Ws[c4 * 4 + 2][row] = v.z; Ws[c4 * 4 + 3][row] = v.w;
        }
        __syncthreads();
#pragma unroll
        for (int k = 0; k < BK; k++) {
            const float4 ra = *reinterpret_cast<const float4*>(&As[k][ty * 4]);
            const float4 rb = *reinterpret_cast<const float4*>(&Ws[k][tx * 4]);
            const float a4[4] = {ra.x, ra.y, ra.z, ra.w};
            const float b4[4] = {rb.x, rb.y, rb.z, rb.w};
#pragma unroll
            for (int i = 0; i < 4; i++)
#pragma unroll
                for (int j = 0; j < 4; j++) acc[i][j] += a4[i] * b4[j];
        }
        __syncthreads();
    }

#pragma unroll
    for (int i = 0; i < 4; i++) {
        int m = m0 + ty * 4 + i;
        if (m >= LF) continue;
#pragma unroll
        for (int j = 0; j < 4; j++) {
            int n = n0 + tx * 4 + j;
            if (n >= Nout) continue;
            float v = acc[i][j];
            if (bias) v += bias[n];
            if (ADDD) v += D[((size_t)b * LF + m) * Nout + n];
            if (RELU) v = fmaxf(v, 0.f);
            if (MULE) v *= E[((size_t)b * LF + m) * Nout + n];
            Cb[(size_t)m * Nout + n] = v;
        }
    }
}

// ---------------- transposed-conv overlap-add ----------------
__global__ void ola_kernel(float* __restrict__ out) {
    const int b = blockIdx.y;
    const int t = blockIdx.x * 256 + threadIdx.x;
    if (t >= SEQ) return;
    const int f0 = t >> 3;
    const int j0 = t & 7;
    float v = 0.f;
    if (f0 < LF)  v += g_of[((size_t)b * LF + f0) * LKER + j0];
    if (f0 >= 1)  v += g_of[((size_t)b * LF + f0 - 1) * LKER + j0 + 8];
    out[(size_t)b * SEQ + t] = v;
}

// ---------------- driver ----------------
extern "C" void kernel_launch(void* const* d_in, const int* in_sizes, int n_in,
                              void* d_out, int out_size) {
    const float* noisy_ac    = (const float*)d_in[0];
    const float* noisy_bc    = (const float*)d_in[1];
    const float* ac_w        = (const float*)d_in[2];
    const float* bc_w        = (const float*)d_in[3];
    const float* me_ln_g     = (const float*)d_in[4];
    const float* me_ln_b     = (const float*)d_in[5];
    const float* me_init_w   = (const float*)d_in[6];
    const float* me_init_b   = (const float*)d_in[7];
    const float* blk_ln_g    = (const float*)d_in[8];
    const float* blk_ln_b    = (const float*)d_in[9];
    const float* blk_act_a   = (const float*)d_in[10];
    const float* inv_w1      = (const float*)d_in[11];
    const float* inv_b1      = (const float*)d_in[12];
    const float* inv_w2      = (const float*)d_in[13];
    const float* inv_b2      = (const float*)d_in[14];
    const float* inv_prelu_a = (const float*)d_in[15];
    const float* skip_w      = (const float*)d_in[16];
    const float* skip_b      = (const float*)d_in[17];
    const float* me_final_w  = (const float*)d_in[18];
    const float* me_final_b  = (const float*)d_in[19];
    const float* dec_w       = (const float*)d_in[20];
    float* out = (float*)d_out;

    float *enc, *x, *xn, *m0, *m1, *of, *dwt;
    cudaGetSymbolAddress((void**)&enc, g_enc);
    cudaGetSymbolAddress((void**)&x,   g_x);
    cudaGetSymbolAddress((void**)&xn,  g_xn);
    cudaGetSymbolAddress((void**)&m0,  g_m0);
    cudaGetSymbolAddress((void**)&m1,  g_m1);
    cudaGetSymbolAddress((void**)&of,  g_of);
    cudaGetSymbolAddress((void**)&dwt, g_dwt);

    // parameter prep
    weff_kernel<<<NBLK * NP * KKER, NCH>>>(inv_w1, inv_b1, inv_w2, inv_b2);
    decwt_kernel<<<LKER, NCH>>>(dec_w);

    // encoder + LN  (writes g_enc, g_x)
    enc_ln_kernel<<<dim3((LF + ENC_FPB - 1) / ENC_FPB, BATCH), 256>>>(
        noisy_ac, noisy_bc, ac_w, bc_w, me_ln_g, me_ln_b);

    // me_init pointwise: g_x -> g_m0   ("x" state lives in g_m0 at loop top)
    gemm_kernel<false, false, false><<<dim3(64, 4, BATCH), 256>>>(
        x, me_init_w, me_init_b, nullptr, nullptr, m0, NCH);

    for (int blk = 0; blk < NBLK; blk++) {
        prelu_ln_kernel<<<dim3((LF + 31) / 32, BATCH), 256>>>(
            m0, xn, blk_act_a, blk_ln_g + blk * NCH, blk_ln_b + blk * NCH, blk);
        inv_kernel<<<dim3((LF + INV_FPB - 1) / INV_FPB, BATCH), 256>>>(xn, x,  inv_prelu_a, blk, 0);
        inv_kernel<<<dim3((LF + INV_FPB - 1) / INV_FPB, BATCH), 256>>>(x,  m1, inv_prelu_a, blk, 1);
        inv_kernel<<<dim3((LF + INV_FPB - 1) / INV_FPB, BATCH), 256>>>(m1, x,  inv_prelu_a, blk, 2);
        // x_new = m (in g_x) + skip(xn)  -> g_m0
        gemm_kernel<false, true, false><<<dim3(64, 4, BATCH), 256>>>(
            xn, skip_w + (size_t)blk * NCH * NCH, skip_b + blk * NCH, x, nullptr, m0, NCH);
    }

    // masked = relu(me_final(x)) * enc  -> g_xn
    gemm_kernel<true, false, true><<<dim3(64, 4, BATCH), 256>>>(
        m0, me_final_w, me_final_b, nullptr, enc, xn, NCH);

    // decoder partials OF[f][j] = masked[f][:] . dec_w[:,j]  -> g_of
    gemm_kernel<false, false, false><<<dim3(64, 1, BATCH), 256>>>(
        xn, dwt, nullptr, nullptr, nullptr, of, LKER);

    // overlap-add -> output
    ola_kernel<<<dim3(SEQ / 256, BATCH), 256>>>(out);
}